// round 12
// baseline (speedup 1.0000x reference)
#include <cuda_runtime.h>
#include <cstdint>

// Problem constants
#define N_NODES   50000
#define N_EDGES   800000
#define TILE_E    64
#define NTILES    12500       // 800000 / 64
#define NUNITS    25000       // tiles x 2 N-halves
#define GRID_EDGE 444         // 3 CTAs x 148 SMs (even -> CTA keeps fixed half)
#define NB50      50176       // 196 * 256 (padded node count for scan)

// ---- U table: [node][512] phys-interleaved; slot1(0:256)=U1(+bias), slot2(256:512)=U2
// phys col p in a 256 block: quad q=p>>3, half h=(p>>2)&1 (0=sig,1=soft), logical l=4q+(p&3)
static __device__ float g_U[(size_t)N_NODES * 512];
static __device__ int   g_count[NB50];     // hist -> local-exclusive scan -> perm cursors
static __device__ int   g_bsum[256];       // block sums -> exclusive block offsets
static __device__ int   g_perm[N_EDGES];   // edge ids sorted by idx1

// ---------------- common helpers ----------------
__device__ __forceinline__ void cp16(uint32_t dst_smem, const void* src) {
    asm volatile("cp.async.cg.shared.global [%0], [%1], 16;" :: "r"(dst_smem), "l"(src));
}
__device__ __forceinline__ void cp16_pol(uint32_t dst_smem, const void* src, uint64_t pol) {
    asm volatile("cp.async.cg.shared.global.L2::cache_hint [%0], [%1], 16, %2;"
                 :: "r"(dst_smem), "l"(src), "l"(pol));
}
__device__ __forceinline__ void cp_commit() { asm volatile("cp.async.commit_group;"); }
__device__ __forceinline__ void cp_wait0()  { asm volatile("cp.async.wait_group 0;"); }

__device__ __forceinline__ uint64_t policy_evict_first() {
    uint64_t p;
    asm volatile("createpolicy.fractional.L2::evict_first.b64 %0, 1.0;" : "=l"(p));
    return p;
}
__device__ __forceinline__ uint64_t policy_evict_last() {
    uint64_t p;
    asm volatile("createpolicy.fractional.L2::evict_last.b64 %0, 1.0;" : "=l"(p));
    return p;
}

__device__ __forceinline__ float2 ldg_el(const float* p, uint64_t pol) {
    float2 v;
    asm volatile("ld.global.nc.L2::cache_hint.v2.f32 {%0,%1}, [%2], %3;"
                 : "=f"(v.x), "=f"(v.y) : "l"(p), "l"(pol));
    return v;
}
__device__ __forceinline__ void stg_el(float* p, float x, float y, uint64_t pol) {
    asm volatile("st.global.L2::cache_hint.v2.f32 [%0], {%1,%2}, %3;"
                 :: "l"(p), "f"(x), "f"(y), "l"(pol) : "memory");
}

__device__ __forceinline__ void mma_tf32(float* c, const uint32_t* a, const uint32_t* b) {
    asm volatile(
        "mma.sync.aligned.m16n8k8.row.col.f32.tf32.tf32.f32 "
        "{%0,%1,%2,%3}, {%4,%5,%6,%7}, {%8,%9}, {%0,%1,%2,%3};"
        : "+f"(c[0]), "+f"(c[1]), "+f"(c[2]), "+f"(c[3])
        : "r"(a[0]), "r"(a[1]), "r"(a[2]), "r"(a[3]), "r"(b[0]), "r"(b[1]));
}

__device__ __forceinline__ void red_add_v2(float* p, float a, float b) {
    asm volatile("red.global.add.v2.f32 [%0], {%1, %2};" :: "l"(p), "f"(a), "f"(b) : "memory");
}

// ---------------- sort kernels ----------------
__global__ void hist_kernel(const int* __restrict__ idx1) {
    int e = blockIdx.x * blockDim.x + threadIdx.x;
    if (e < N_EDGES) atomicAdd(&g_count[idx1[e]], 1);
}

__global__ void scan_a_kernel() {
    __shared__ int s[256];
    int t = threadIdx.x, b = blockIdx.x;
    int i = b * 256 + t;
    int c = g_count[i];
    s[t] = c; __syncthreads();
#pragma unroll
    for (int d = 1; d < 256; d <<= 1) {
        int v = (t >= d) ? s[t - d] : 0; __syncthreads();
        s[t] += v; __syncthreads();
    }
    g_count[i] = s[t] - c;
    if (t == 255) g_bsum[b] = s[255];
}

__global__ void scan_b_kernel() {
    __shared__ int s[256];
    int t = threadIdx.x;
    int c = (t < 196) ? g_bsum[t] : 0;
    s[t] = c; __syncthreads();
#pragma unroll
    for (int d = 1; d < 256; d <<= 1) {
        int v = (t >= d) ? s[t - d] : 0; __syncthreads();
        s[t] += v; __syncthreads();
    }
    g_bsum[t] = s[t] - c;
}

__global__ void perm_kernel(const int* __restrict__ idx1) {
    int e = blockIdx.x * blockDim.x + threadIdx.x;
    if (e < N_EDGES) {
        int n = idx1[e];
        int local = atomicAdd(&g_count[n], 1);
        g_perm[local + g_bsum[n >> 8]] = e;
    }
}

// ---------------- U precompute (fused: zero g_count + residual copy + GEMM) ----------------
#define UG_ASTR 36
#define UG_BSTR 136
#define UG_A0   0
#define UG_A1   4608
#define UG_B0   9216
#define UG_B1   13568
#define UG_SMEMF 17920

__global__ void __launch_bounds__(256) u_gemm_kernel(
    const float* __restrict__ sites,
    const float* __restrict__ W_sig, const float* __restrict__ b_sig,
    const float* __restrict__ W_soft, const float* __restrict__ b_soft,
    float* __restrict__ out)
{
    extern __shared__ float smf[];
    uint32_t sbase = (uint32_t)__cvta_generic_to_shared(smf);

    const int tid = threadIdx.x, wid = tid >> 5, lane = tid & 31;
    const int g = lane >> 2, cc = lane & 3;
    const int wm = wid >> 1, wn = wid & 1;
    const int bm = blockIdx.x, by = blockIdx.y;
    const int row0 = bm * 128;
    const uint64_t pol_last = policy_evict_last();

    {
        int gid = (by * gridDim.x + bm) * 256 + tid;
        int nthr = gridDim.x * gridDim.y * 256;
        if (gid < NB50) g_count[gid] = 0;
        const float4* s4 = (const float4*)sites;
        float4* o4 = (float4*)out;
        for (int i = gid; i < (N_NODES * 128) / 4; i += nthr) o4[i] = s4[i];
    }

    auto load_stage = [&](int s) {
        uint32_t abuf = sbase + (uint32_t)(((s & 1) ? UG_A1 : UG_A0) * 4);
        uint32_t bbuf = sbase + (uint32_t)(((s & 1) ? UG_B1 : UG_B0) * 4);
#pragma unroll
        for (int j = 0; j < 4; j++) {
            int q = tid + j * 256;
            int r = q >> 3, cx = q & 7;
            int grow = row0 + r; if (grow >= N_NODES) grow = N_NODES - 1;
            cp16(abuf + (uint32_t)((r * UG_ASTR + cx * 4) * 4),
                 sites + (size_t)grow * 128 + s * 32 + cx * 4);
        }
#pragma unroll
        for (int j = 0; j < 4; j++) {
            int q = tid + j * 256;
            int k = q >> 5, cq = q & 31;
            int P0 = by * 128 + cq * 4;
            int slot = P0 >> 8, p = P0 & 255;
            int h = (p >> 2) & 1, qd = p >> 3;
            const float* W = h ? W_soft : W_sig;
            cp16(bbuf + (uint32_t)((k * UG_BSTR + cq * 4) * 4),
                 W + (size_t)(slot * 128 + s * 32 + k) * 128 + qd * 4);
        }
    };

    load_stage(0); cp_commit();
    load_stage(1); cp_commit();

    float acc[2][8][4];
#pragma unroll
    for (int mt = 0; mt < 2; mt++)
#pragma unroll
        for (int nt = 0; nt < 8; nt++)
#pragma unroll
            for (int u = 0; u < 4; u++) acc[mt][nt][u] = 0.0f;

    for (int s = 0; s < 4; ++s) {
        if (s < 3) { asm volatile("cp.async.wait_group 1;"); } else cp_wait0();
        __syncthreads();
        const float* As = smf + ((s & 1) ? UG_A1 : UG_A0);
        const float* Bs = smf + ((s & 1) ? UG_B1 : UG_B0);
#pragma unroll
        for (int k8 = 0; k8 < 4; k8++) {
            const int k0 = k8 * 8;
            uint32_t a[2][4];
#pragma unroll
            for (int mt = 0; mt < 2; mt++) {
                const uint32_t* ap = (const uint32_t*)(As + (32 * wm + 16 * mt + g) * UG_ASTR + k0 + cc);
                a[mt][0] = ap[0]; a[mt][1] = ap[8 * UG_ASTR];
                a[mt][2] = ap[4]; a[mt][3] = ap[8 * UG_ASTR + 4];
            }
            uint32_t b[8][2];
#pragma unroll
            for (int nt = 0; nt < 8; nt++) {
                const uint32_t* bp = (const uint32_t*)(Bs + (k0 + cc) * UG_BSTR + 64 * wn + 8 * nt + g);
                b[nt][0] = bp[0]; b[nt][1] = bp[4 * UG_BSTR];
            }
#pragma unroll
            for (int mt = 0; mt < 2; mt++)
#pragma unroll
                for (int nt = 0; nt < 8; nt++)
                    mma_tf32(acc[mt][nt], a[mt], b[nt]);
        }
        __syncthreads();
        if (s + 2 < 4) { load_stage(s + 2); cp_commit(); }
    }

#pragma unroll
    for (int mt = 0; mt < 2; mt++) {
        int r_lo = 32 * wm + 16 * mt + g;
        int grow_lo = row0 + r_lo, grow_hi = grow_lo + 8;
#pragma unroll
        for (int nt = 0; nt < 8; nt++) {
            int col = 64 * wn + 8 * nt + 2 * cc;
            int P = by * 128 + col;
            float bb0 = 0.0f, bb1 = 0.0f;
            if (by < 2) {
                int p = P & 255;
                int h = (p >> 2) & 1;
                int l = ((p >> 3) << 2) | (p & 3);
                const float* bv = h ? b_soft : b_sig;
                bb0 = bv[l]; bb1 = bv[l + 1];
            }
            if (grow_lo < N_NODES)
                stg_el(g_U + (size_t)grow_lo * 512 + P,
                       acc[mt][nt][0] + bb0, acc[mt][nt][1] + bb1, pol_last);
            if (grow_hi < N_NODES)
                stg_el(g_U + (size_t)grow_hi * 512 + P,
                       acc[mt][nt][2] + bb0, acc[mt][nt][3] + bb1, pol_last);
        }
    }
}

// ---------------- edge kernel (sorted, N-split): unit = (tile, half). Each CTA owns a fixed
// 128-phys-col half end-to-end (GEMM, gate, scatter) -> 70KB smem -> 3 CTAs/SM.
#define EG_ASTR  68
#define EG_BSTR  132
#define EG_OFF_B    0            // 64 x 132 = 8448 fl (loaded once per CTA)
#define EG_OFF_A0   8448         // 64 x 68 = 4352 fl per buffer
#define EG_OFF_A1   12800
#define EG_OFF_IDX  17152        // 2 buffers x 192 ints
#define EG_SMEMF    17600
#define EG_SMEMB    (EG_SMEMF * 4)   // 70400

__global__ void __launch_bounds__(256, 3) edge_gate_kernel(
    const float* __restrict__ bonds,
    const float* __restrict__ W_sig, const float* __restrict__ W_soft,
    const int* __restrict__ idx1, const int* __restrict__ idx2,
    float* __restrict__ out)
{
    extern __shared__ float smf[];
    uint32_t sbase = (uint32_t)__cvta_generic_to_shared(smf);

    const int tid = threadIdx.x, wid = tid >> 5, lane = tid & 31;
    const int g = lane >> 2, cc = lane & 3;
    const int wm = wid >> 2, wn = wid & 3;       // 2x4 warp grid, warp tile 32(M) x 32(phys N)
    const int nhalf = blockIdx.x & 1;            // fixed: GRID_EDGE even => u&1 invariant
    const uint64_t pol_first = policy_evict_first();
    const uint64_t pol_last  = policy_evict_last();

    // segmented-reduction lane map (unchanged: M-tile structure identical)
    const int c0 = cc & 1;
    const int rr = g + ((cc >> 1) << 3);         // 0..15
    int srcl[4];
#pragma unroll
    for (int st = 0; st < 4; st++) {
        int rp = (rr + (1 << st)) & 15;
        srcl[st] = ((rp & 7) << 2) | ((rp >> 3) << 1) | c0;
    }

    // load B half (Wb rows 256:320, phys cols [nhalf*128, nhalf*128+128)): 2048 chunks
#pragma unroll
    for (int j = 0; j < 8; j++) {
        int q = tid + j * 256;
        int k = q >> 5, cq = q & 31;             // local quad cq -> phys col 4*(nhalf*32+cq)
        int cqg = nhalf * 32 + cq;
        int h = cqg & 1, qd = cqg >> 1;
        const float* W = h ? W_soft : W_sig;
        cp16(sbase + (uint32_t)((k * EG_BSTR + cq * 4) * 4),
             W + (size_t)(256 + k) * 128 + qd * 4);
    }

    int* islot = (int*)(smf + EG_OFF_IDX);   // [buf*192 + {perm:0, i1:64, i2:128}]

    auto load_A_cp = [&](int buf) {
        const int* sp = islot + buf * 192;
        uint32_t abuf = sbase + (uint32_t)(((buf ? EG_OFF_A1 : EG_OFF_A0)) * 4);
#pragma unroll
        for (int j = 0; j < 4; j++) {
            int q = tid + j * 256;
            int r = q >> 4, cx = q & 15;
            cp16_pol(abuf + (uint32_t)((r * EG_ASTR + cx * 4) * 4),
                     bonds + (size_t)sp[r] * 64 + cx * 4, pol_first);
        }
    };

    // ---- prologue ----
    int unit = blockIdx.x;
    if (tid < 64) {
        int p = g_perm[(unit >> 1) * TILE_E + tid];
        islot[tid] = p; islot[64 + tid] = idx1[p]; islot[128 + tid] = idx2[p];
    }
    __syncthreads();
    load_A_cp(0); cp_commit();

    int p_r = 0, a_r = 0, b_r = 0;
    {
        int nx = unit + GRID_EDGE;
        if (tid < 64 && nx < NUNITS) {
            p_r = g_perm[(nx >> 1) * TILE_E + tid]; a_r = idx1[p_r]; b_r = idx2[p_r];
        }
    }

    int it = 0;
    while (true) {
        int buf = it & 1;
        int next = unit + GRID_EDGE;
        bool have_next = (next < NUNITS);

        cp_wait0(); __syncthreads();

        if (have_next && tid < 64) {
            int* d = islot + (buf ^ 1) * 192;
            d[tid] = p_r; d[64 + tid] = a_r; d[128 + tid] = b_r;
        }
        __syncthreads();
        if (have_next) { load_A_cp(buf ^ 1); cp_commit(); }

        int nn = next + GRID_EDGE;
        if (have_next && tid < 64 && nn < NUNITS) {   // hidden under GEMM
            p_r = g_perm[(nn >> 1) * TILE_E + tid]; a_r = idx1[p_r]; b_r = idx2[p_r];
        }

        const float* As = smf + (buf ? EG_OFF_A1 : EG_OFF_A0);
        const float* Bs = smf + EG_OFF_B;

        float acc[2][4][4];
#pragma unroll
        for (int mt = 0; mt < 2; mt++)
#pragma unroll
            for (int nt = 0; nt < 4; nt++)
#pragma unroll
                for (int u = 0; u < 4; u++) acc[mt][nt][u] = 0.0f;

#pragma unroll
        for (int k8 = 0; k8 < 8; k8++) {
            const int k0 = k8 * 8;
            uint32_t a[2][4];
#pragma unroll
            for (int mt = 0; mt < 2; mt++) {
                const uint32_t* ap = (const uint32_t*)(As + (32 * wm + 16 * mt + g) * EG_ASTR + k0 + cc);
                a[mt][0] = ap[0]; a[mt][1] = ap[8 * EG_ASTR];
                a[mt][2] = ap[4]; a[mt][3] = ap[8 * EG_ASTR + 4];
            }
            uint32_t b[4][2];
#pragma unroll
            for (int nt = 0; nt < 4; nt++) {
                const uint32_t* bp = (const uint32_t*)(Bs + (k0 + cc) * EG_BSTR + 32 * wn + 8 * nt + g);
                b[nt][0] = bp[0]; b[nt][1] = bp[4 * EG_BSTR];
            }
#pragma unroll
            for (int mt = 0; mt < 2; mt++)
#pragma unroll
                for (int nt = 0; nt < 4; nt++)
                    mma_tf32(acc[mt][nt], a[mt], b[nt]);
        }

        // ---- epilogue: this CTA's 128 phys cols; gate + seg-reduce + head scatter ----
        const int* sidx = islot + buf * 192;
        const int cb = 32 * wn + 2 * cc;
        const int ubase = nhalf * 128;           // phys col offset into U 256-block
#pragma unroll
        for (int mt = 0; mt < 2; mt++) {
            int r_lo = 32 * wm + 16 * mt + g;
            int r_hi = r_lo + 8;
            int i1lo = sidx[64 + r_lo], i2lo = sidx[128 + r_lo];
            int i1hi = sidx[64 + r_hi], i2hi = sidx[128 + r_hi];
            const float* U1lo = g_U + (size_t)i1lo * 512 + ubase;
            const float* U2lo = g_U + (size_t)i2lo * 512 + 256 + ubase;
            const float* U1hi = g_U + (size_t)i1hi * 512 + ubase;
            const float* U2hi = g_U + (size_t)i2hi * 512 + 256 + ubase;
            float* outlo = out + (size_t)i1lo * 128 + nhalf * 64;
            float* outhi = out + (size_t)i1hi * 128 + nhalf * 64;

            int row_g = 32 * wm + 16 * mt + rr;
            int my_i1 = (cc & 2) ? i1hi : i1lo;
            bool head = (rr == 0) || (sidx[64 + row_g - 1] != my_i1);
            bool samep[4];
#pragma unroll
            for (int st = 0; st < 4; st++) {
                int i1p = __shfl_sync(0xFFFFFFFFu, my_i1, srcl[st]);
                samep[st] = ((rr + (1 << st)) < 16) && (i1p == my_i1);
            }
            float* dst = (cc & 2) ? outhi : outlo;

#pragma unroll
            for (int nt = 0; nt < 4; nt++) {
                int c = cb + 8 * nt;
                float2 ua = ldg_el(U1lo + c, pol_last);
                float2 ub = ldg_el(U2lo + c, pol_last);
                float2 va = ldg_el(U1hi + c, pol_last);
                float2 vb = ldg_el(U2hi + c, pol_last);
                float x0 = acc[mt][nt][0] + ua.x + ub.x;
                float x1 = acc[mt][nt][1] + ua.y + ub.y;
                float y0 = acc[mt][nt][2] + va.x + vb.x;
                float y1 = acc[mt][nt][3] + va.y + vb.y;
                float rx0 = __shfl_xor_sync(0xFFFFFFFFu, x0, 2);
                float rx1 = __shfl_xor_sync(0xFFFFFFFFu, x1, 2);
                float ry0 = __shfl_xor_sync(0xFFFFFFFFu, y0, 2);
                float ry1 = __shfl_xor_sync(0xFFFFFFFFu, y1, 2);
                float sg0, sg1, sf0, sf1;
                if ((cc & 2) == 0) {
                    sg0 = x0; sg1 = x1; sf0 = rx0; sf1 = rx1;
                } else {
                    sg0 = ry0; sg1 = ry1; sf0 = y0; sf1 = y1;
                }
                float v0 = (1.0f / (1.0f + __expf(-sg0))) * fmaxf(sf0, 0.0f);
                float v1 = (1.0f / (1.0f + __expf(-sg1))) * fmaxf(sf1, 0.0f);

#pragma unroll
                for (int st = 0; st < 4; st++) {
                    float t0 = __shfl_sync(0xFFFFFFFFu, v0, srcl[st]);
                    float t1 = __shfl_sync(0xFFFFFFFFu, v1, srcl[st]);
                    if (samep[st]) { v0 += t0; v1 += t1; }
                }
                if (head) {
                    int gcol = 16 * wn + 4 * nt + 2 * c0;   // logical col within 64-col half
                    red_add_v2(dst + gcol, v0, v1);
                }
            }
        }

        if (!have_next) break;
        unit = next; ++it;
    }
}

// ---------------- launch ----------------
extern "C" void kernel_launch(void* const* d_in, const int* in_sizes, int n_in,
                              void* d_out, int out_size) {
    const float* sites  = (const float*)d_in[0];
    const float* bonds  = (const float*)d_in[1];
    const float* W_sig  = (const float*)d_in[2];
    const float* b_sig  = (const float*)d_in[3];
    const float* W_soft = (const float*)d_in[4];
    const float* b_soft = (const float*)d_in[5];
    const int*   idx1   = (const int*)d_in[6];
    const int*   idx2   = (const int*)d_in[7];
    float* out = (float*)d_out;

    cudaFuncSetAttribute(u_gemm_kernel, cudaFuncAttributeMaxDynamicSharedMemorySize, UG_SMEMF * 4);
    cudaFuncSetAttribute(edge_gate_kernel, cudaFuncAttributeMaxDynamicSharedMemorySize, EG_SMEMB);

    // 1) U = sites @ Wcat (fused: zero g_count + out=sites residual copy)
    u_gemm_kernel<<<dim3((N_NODES + 127) / 128, 4), 256, UG_SMEMF * 4>>>(
        sites, W_sig, b_sig, W_soft, b_soft, out);

    // 2-5) counting sort of edges by idx1
    hist_kernel<<<N_EDGES / 256, 256>>>(idx1);
    scan_a_kernel<<<NB50 / 256, 256>>>();
    scan_b_kernel<<<1, 256>>>();
    perm_kernel<<<N_EDGES / 256, 256>>>(idx1);

    // 6) edges (sorted, N-split): bonds[perm] @ Wb-half + U gather + gate + seg-reduce + scatter
    edge_gate_kernel<<<GRID_EDGE, 256, EG_SMEMB>>>(
        bonds, W_sig, W_soft, idx1, idx2, out);
}

// round 13
// speedup vs baseline: 1.1561x; 1.1561x over previous
#include <cuda_runtime.h>
#include <cstdint>

// Problem constants
#define N_NODES   50000
#define N_EDGES   800000
#define TILE_E    64
#define NTILES    12500       // 800000 / 64
#define GRID_EDGE 296         // 2 CTAs x 148 SMs
#define NB50      50176       // 196 * 256 (padded node count for scan)

// ---- U table: [node][512] phys-interleaved; slot1(0:256)=U1(+bias), slot2(256:512)=U2
static __device__ float g_U[(size_t)N_NODES * 512];
static __device__ int   g_count[NB50];
static __device__ int   g_bsum[256];
static __device__ int   g_perm[N_EDGES];

// ---------------- common helpers ----------------
__device__ __forceinline__ void cp16(uint32_t dst_smem, const void* src) {
    asm volatile("cp.async.cg.shared.global [%0], [%1], 16;" :: "r"(dst_smem), "l"(src));
}
__device__ __forceinline__ void cp16_pol(uint32_t dst_smem, const void* src, uint64_t pol) {
    asm volatile("cp.async.cg.shared.global.L2::cache_hint [%0], [%1], 16, %2;"
                 :: "r"(dst_smem), "l"(src), "l"(pol));
}
__device__ __forceinline__ void cp_commit() { asm volatile("cp.async.commit_group;"); }
__device__ __forceinline__ void cp_wait0()  { asm volatile("cp.async.wait_group 0;"); }

__device__ __forceinline__ uint64_t policy_evict_first() {
    uint64_t p;
    asm volatile("createpolicy.fractional.L2::evict_first.b64 %0, 1.0;" : "=l"(p));
    return p;
}
__device__ __forceinline__ uint64_t policy_evict_last() {
    uint64_t p;
    asm volatile("createpolicy.fractional.L2::evict_last.b64 %0, 1.0;" : "=l"(p));
    return p;
}

__device__ __forceinline__ float2 ldg_el(const float* p, uint64_t pol) {
    float2 v;
    asm volatile("ld.global.nc.L2::cache_hint.v2.f32 {%0,%1}, [%2], %3;"
                 : "=f"(v.x), "=f"(v.y) : "l"(p), "l"(pol));
    return v;
}
__device__ __forceinline__ void stg_el(float* p, float x, float y, uint64_t pol) {
    asm volatile("st.global.L2::cache_hint.v2.f32 [%0], {%1,%2}, %3;"
                 :: "l"(p), "f"(x), "f"(y), "l"(pol) : "memory");
}

__device__ __forceinline__ void mma_tf32(float* c, const uint32_t* a, const uint32_t* b) {
    asm volatile(
        "mma.sync.aligned.m16n8k8.row.col.f32.tf32.tf32.f32 "
        "{%0,%1,%2,%3}, {%4,%5,%6,%7}, {%8,%9}, {%0,%1,%2,%3};"
        : "+f"(c[0]), "+f"(c[1]), "+f"(c[2]), "+f"(c[3])
        : "r"(a[0]), "r"(a[1]), "r"(a[2]), "r"(a[3]), "r"(b[0]), "r"(b[1]));
}

__device__ __forceinline__ void red_add_v2(float* p, float a, float b) {
    asm volatile("red.global.add.v2.f32 [%0], {%1, %2};" :: "l"(p), "f"(a), "f"(b) : "memory");
}

// ---------------- sort kernels ----------------
__global__ void hist_kernel(const int* __restrict__ idx1) {
    int e = blockIdx.x * blockDim.x + threadIdx.x;
    if (e < N_EDGES) atomicAdd(&g_count[idx1[e]], 1);
}

__global__ void scan_a_kernel() {
    __shared__ int s[256];
    int t = threadIdx.x, b = blockIdx.x;
    int i = b * 256 + t;
    int c = g_count[i];
    s[t] = c; __syncthreads();
#pragma unroll
    for (int d = 1; d < 256; d <<= 1) {
        int v = (t >= d) ? s[t - d] : 0; __syncthreads();
        s[t] += v; __syncthreads();
    }
    g_count[i] = s[t] - c;
    if (t == 255) g_bsum[b] = s[255];
}

__global__ void scan_b_kernel() {
    __shared__ int s[256];
    int t = threadIdx.x;
    int c = (t < 196) ? g_bsum[t] : 0;
    s[t] = c; __syncthreads();
#pragma unroll
    for (int d = 1; d < 256; d <<= 1) {
        int v = (t >= d) ? s[t - d] : 0; __syncthreads();
        s[t] += v; __syncthreads();
    }
    g_bsum[t] = s[t] - c;
}

__global__ void perm_kernel(const int* __restrict__ idx1) {
    int e = blockIdx.x * blockDim.x + threadIdx.x;
    if (e < N_EDGES) {
        int n = idx1[e];
        int local = atomicAdd(&g_count[n], 1);
        g_perm[local + g_bsum[n >> 8]] = e;
    }
}

// ---------------- U precompute (fused: zero g_count + residual copy + GEMM) ----------------
#define UG_ASTR 36
#define UG_BSTR 136
#define UG_A0   0
#define UG_A1   4608
#define UG_B0   9216
#define UG_B1   13568
#define UG_SMEMF 17920

__global__ void __launch_bounds__(256) u_gemm_kernel(
    const float* __restrict__ sites,
    const float* __restrict__ W_sig, const float* __restrict__ b_sig,
    const float* __restrict__ W_soft, const float* __restrict__ b_soft,
    float* __restrict__ out)
{
    extern __shared__ float smf[];
    uint32_t sbase = (uint32_t)__cvta_generic_to_shared(smf);

    const int tid = threadIdx.x, wid = tid >> 5, lane = tid & 31;
    const int g = lane >> 2, cc = lane & 3;
    const int wm = wid >> 1, wn = wid & 1;
    const int bm = blockIdx.x, by = blockIdx.y;
    const int row0 = bm * 128;
    const uint64_t pol_last = policy_evict_last();

    {
        int gid = (by * gridDim.x + bm) * 256 + tid;
        int nthr = gridDim.x * gridDim.y * 256;
        if (gid < NB50) g_count[gid] = 0;
        const float4* s4 = (const float4*)sites;
        float4* o4 = (float4*)out;
        for (int i = gid; i < (N_NODES * 128) / 4; i += nthr) o4[i] = s4[i];
    }

    auto load_stage = [&](int s) {
        uint32_t abuf = sbase + (uint32_t)(((s & 1) ? UG_A1 : UG_A0) * 4);
        uint32_t bbuf = sbase + (uint32_t)(((s & 1) ? UG_B1 : UG_B0) * 4);
#pragma unroll
        for (int j = 0; j < 4; j++) {
            int q = tid + j * 256;
            int r = q >> 3, cx = q & 7;
            int grow = row0 + r; if (grow >= N_NODES) grow = N_NODES - 1;
            cp16(abuf + (uint32_t)((r * UG_ASTR + cx * 4) * 4),
                 sites + (size_t)grow * 128 + s * 32 + cx * 4);
        }
#pragma unroll
        for (int j = 0; j < 4; j++) {
            int q = tid + j * 256;
            int k = q >> 5, cq = q & 31;
            int P0 = by * 128 + cq * 4;
            int slot = P0 >> 8, p = P0 & 255;
            int h = (p >> 2) & 1, qd = p >> 3;
            const float* W = h ? W_soft : W_sig;
            cp16(bbuf + (uint32_t)((k * UG_BSTR + cq * 4) * 4),
                 W + (size_t)(slot * 128 + s * 32 + k) * 128 + qd * 4);
        }
    };

    load_stage(0); cp_commit();
    load_stage(1); cp_commit();

    float acc[2][8][4];
#pragma unroll
    for (int mt = 0; mt < 2; mt++)
#pragma unroll
        for (int nt = 0; nt < 8; nt++)
#pragma unroll
            for (int u = 0; u < 4; u++) acc[mt][nt][u] = 0.0f;

    for (int s = 0; s < 4; ++s) {
        if (s < 3) { asm volatile("cp.async.wait_group 1;"); } else cp_wait0();
        __syncthreads();
        const float* As = smf + ((s & 1) ? UG_A1 : UG_A0);
        const float* Bs = smf + ((s & 1) ? UG_B1 : UG_B0);
#pragma unroll
        for (int k8 = 0; k8 < 4; k8++) {
            const int k0 = k8 * 8;
            uint32_t a[2][4];
#pragma unroll
            for (int mt = 0; mt < 2; mt++) {
                const uint32_t* ap = (const uint32_t*)(As + (32 * wm + 16 * mt + g) * UG_ASTR + k0 + cc);
                a[mt][0] = ap[0]; a[mt][1] = ap[8 * UG_ASTR];
                a[mt][2] = ap[4]; a[mt][3] = ap[8 * UG_ASTR + 4];
            }
            uint32_t b[8][2];
#pragma unroll
            for (int nt = 0; nt < 8; nt++) {
                const uint32_t* bp = (const uint32_t*)(Bs + (k0 + cc) * UG_BSTR + 64 * wn + 8 * nt + g);
                b[nt][0] = bp[0]; b[nt][1] = bp[4 * UG_BSTR];
            }
#pragma unroll
            for (int mt = 0; mt < 2; mt++)
#pragma unroll
                for (int nt = 0; nt < 8; nt++)
                    mma_tf32(acc[mt][nt], a[mt], b[nt]);
        }
        __syncthreads();
        if (s + 2 < 4) { load_stage(s + 2); cp_commit(); }
    }

#pragma unroll
    for (int mt = 0; mt < 2; mt++) {
        int r_lo = 32 * wm + 16 * mt + g;
        int grow_lo = row0 + r_lo, grow_hi = grow_lo + 8;
#pragma unroll
        for (int nt = 0; nt < 8; nt++) {
            int col = 64 * wn + 8 * nt + 2 * cc;
            int P = by * 128 + col;
            float bb0 = 0.0f, bb1 = 0.0f;
            if (by < 2) {
                int p = P & 255;
                int h = (p >> 2) & 1;
                int l = ((p >> 3) << 2) | (p & 3);
                const float* bv = h ? b_soft : b_sig;
                bb0 = bv[l]; bb1 = bv[l + 1];
            }
            if (grow_lo < N_NODES)
                stg_el(g_U + (size_t)grow_lo * 512 + P,
                       acc[mt][nt][0] + bb0, acc[mt][nt][1] + bb1, pol_last);
            if (grow_hi < N_NODES)
                stg_el(g_U + (size_t)grow_hi * 512 + P,
                       acc[mt][nt][2] + bb0, acc[mt][nt][3] + bb1, pol_last);
        }
    }
}

// ---------------- edge kernel (sorted, full-N, two-phase epilogue) ----------------
#define EG_ASTR  68
#define EG_BSTR  264
#define EG_OFF_B    0            // 64 x 264 = 16896 fl (loaded once)
#define EG_OFF_A0   16896        // 64 x 68 = 4352 fl per buffer
#define EG_OFF_IDX  25600        // 2 buffers x 192 ints
#define EG_SMEMF    25984
#define EG_SMEMB    (EG_SMEMF * 4)   // 103936

__global__ void __launch_bounds__(256, 2) edge_gate_kernel(
    const float* __restrict__ bonds,
    const float* __restrict__ W_sig, const float* __restrict__ W_soft,
    const int* __restrict__ idx1, const int* __restrict__ idx2,
    float* __restrict__ out)
{
    extern __shared__ float smf[];
    uint32_t sbase = (uint32_t)__cvta_generic_to_shared(smf);

    const int tid = threadIdx.x, wid = tid >> 5, lane = tid & 31;
    const int g = lane >> 2, cc = lane & 3;
    const int wm = wid >> 2, wn = wid & 3;       // 2x4 warp grid, warp tile 32x64
    const uint64_t pol_first = policy_evict_first();
    const uint64_t pol_last  = policy_evict_last();

    // segmented-reduction lane map
    const int c0 = cc & 1;
    const int rr = g + ((cc >> 1) << 3);         // 0..15
    int srcl[4];
#pragma unroll
    for (int st = 0; st < 4; st++) {
        int rp = (rr + (1 << st)) & 15;
        srcl[st] = ((rp & 7) << 2) | ((rp >> 3) << 1) | c0;
    }

    // load B (Wb rows 256:320, phys-interleaved cols) once: 4096 chunks
#pragma unroll
    for (int j = 0; j < 16; j++) {
        int q = tid + j * 256;
        int k = q >> 6, cq = q & 63;
        int h = cq & 1, qd = cq >> 1;
        const float* W = h ? W_soft : W_sig;
        cp16(sbase + (uint32_t)((k * EG_BSTR + cq * 4) * 4),
             W + (size_t)(256 + k) * 128 + qd * 4);
    }

    int* islot = (int*)(smf + EG_OFF_IDX);

    auto load_A_cp = [&](int buf) {
        const int* sp = islot + buf * 192;
        uint32_t abuf = sbase + (uint32_t)((EG_OFF_A0 + buf * 4352) * 4);
#pragma unroll
        for (int j = 0; j < 4; j++) {
            int q = tid + j * 256;
            int r = q >> 4, cx = q & 15;
            cp16_pol(abuf + (uint32_t)((r * EG_ASTR + cx * 4) * 4),
                     bonds + (size_t)sp[r] * 64 + cx * 4, pol_first);
        }
    };

    // ---- prologue ----
    int tile = blockIdx.x;
    if (tid < 64) {
        int p = g_perm[tile * TILE_E + tid];
        islot[tid] = p; islot[64 + tid] = idx1[p]; islot[128 + tid] = idx2[p];
    }
    __syncthreads();
    load_A_cp(0); cp_commit();

    int p_r = 0, a_r = 0, b_r = 0;
    {
        int nx = tile + GRID_EDGE;
        if (tid < 64 && nx < NTILES) {
            p_r = g_perm[nx * TILE_E + tid]; a_r = idx1[p_r]; b_r = idx2[p_r];
        }
    }

    int it = 0;
    while (true) {
        int buf = it & 1;
        int next = tile + GRID_EDGE;
        bool have_next = (next < NTILES);

        cp_wait0(); __syncthreads();

        if (have_next && tid < 64) {
            int* d = islot + (buf ^ 1) * 192;
            d[tid] = p_r; d[64 + tid] = a_r; d[128 + tid] = b_r;
        }
        __syncthreads();
        if (have_next) { load_A_cp(buf ^ 1); cp_commit(); }

        int nn = next + GRID_EDGE;
        if (have_next && tid < 64 && nn < NTILES) {
            p_r = g_perm[nn * TILE_E + tid]; a_r = idx1[p_r]; b_r = idx2[p_r];
        }

        const float* As = smf + EG_OFF_A0 + buf * 4352;
        const float* Bs = smf + EG_OFF_B;

        float acc[2][8][4];
#pragma unroll
        for (int mt = 0; mt < 2; mt++)
#pragma unroll
            for (int nt = 0; nt < 8; nt++)
#pragma unroll
                for (int u = 0; u < 4; u++) acc[mt][nt][u] = 0.0f;

#pragma unroll
        for (int k8 = 0; k8 < 8; k8++) {
            const int k0 = k8 * 8;
            uint32_t a[2][4];
#pragma unroll
            for (int mt = 0; mt < 2; mt++) {
                const uint32_t* ap = (const uint32_t*)(As + (32 * wm + 16 * mt + g) * EG_ASTR + k0 + cc);
                a[mt][0] = ap[0]; a[mt][1] = ap[8 * EG_ASTR];
                a[mt][2] = ap[4]; a[mt][3] = ap[8 * EG_ASTR + 4];
            }
            uint32_t b[8][2];
#pragma unroll
            for (int nt = 0; nt < 8; nt++) {
                const uint32_t* bp = (const uint32_t*)(Bs + (k0 + cc) * EG_BSTR + 64 * wn + 8 * nt + g);
                b[nt][0] = bp[0]; b[nt][1] = bp[4 * EG_BSTR];
            }
#pragma unroll
            for (int mt = 0; mt < 2; mt++)
#pragma unroll
                for (int nt = 0; nt < 8; nt++)
                    mma_tf32(acc[mt][nt], a[mt], b[nt]);
        }

        const int* sidx = islot + buf * 192;
        const int cb = 64 * wn + 2 * cc;

        // ---- epilogue PHASE 1: accumulate U into acc (all 64 loads independent -> max MLP) ----
#pragma unroll
        for (int mt = 0; mt < 2; mt++) {
            int r_lo = 32 * wm + 16 * mt + g;
            int r_hi = r_lo + 8;
            const float* U1lo = g_U + (size_t)sidx[64 + r_lo] * 512;
            const float* U2lo = g_U + (size_t)sidx[128 + r_lo] * 512 + 256;
            const float* U1hi = g_U + (size_t)sidx[64 + r_hi] * 512;
            const float* U2hi = g_U + (size_t)sidx[128 + r_hi] * 512 + 256;
#pragma unroll
            for (int nt = 0; nt < 8; nt++) {
                int c = cb + 8 * nt;
                float2 ua = ldg_el(U1lo + c, pol_last);
                float2 ub = ldg_el(U2lo + c, pol_last);
                float2 va = ldg_el(U1hi + c, pol_last);
                float2 vb = ldg_el(U2hi + c, pol_last);
                acc[mt][nt][0] += ua.x + ub.x;
                acc[mt][nt][1] += ua.y + ub.y;
                acc[mt][nt][2] += va.x + vb.x;
                acc[mt][nt][3] += va.y + vb.y;
            }
        }

        // ---- epilogue PHASE 2: gate + seg-reduce + head-only scatter (compute-only) ----
#pragma unroll
        for (int mt = 0; mt < 2; mt++) {
            int r_lo = 32 * wm + 16 * mt + g;
            int r_hi = r_lo + 8;
            int i1lo = sidx[64 + r_lo];
            int i1hi = sidx[64 + r_hi];
            float* outlo = out + (size_t)i1lo * 128;
            float* outhi = out + (size_t)i1hi * 128;

            int row_g = 32 * wm + 16 * mt + rr;
            int my_i1 = (cc & 2) ? i1hi : i1lo;
            bool head = (rr == 0) || (sidx[64 + row_g - 1] != my_i1);
            bool samep[4];
#pragma unroll
            for (int st = 0; st < 4; st++) {
                int i1p = __shfl_sync(0xFFFFFFFFu, my_i1, srcl[st]);
                samep[st] = ((rr + (1 << st)) < 16) && (i1p == my_i1);
            }
            float* dst = (cc & 2) ? outhi : outlo;

#pragma unroll
            for (int nt = 0; nt < 8; nt++) {
                float x0 = acc[mt][nt][0], x1 = acc[mt][nt][1];
                float y0 = acc[mt][nt][2], y1 = acc[mt][nt][3];
                float rx0 = __shfl_xor_sync(0xFFFFFFFFu, x0, 2);
                float rx1 = __shfl_xor_sync(0xFFFFFFFFu, x1, 2);
                float ry0 = __shfl_xor_sync(0xFFFFFFFFu, y0, 2);
                float ry1 = __shfl_xor_sync(0xFFFFFFFFu, y1, 2);
                float sg0, sg1, sf0, sf1;
                if ((cc & 2) == 0) {
                    sg0 = x0; sg1 = x1; sf0 = rx0; sf1 = rx1;
                } else {
                    sg0 = ry0; sg1 = ry1; sf0 = y0; sf1 = y1;
                }
                float v0 = (1.0f / (1.0f + __expf(-sg0))) * fmaxf(sf0, 0.0f);
                float v1 = (1.0f / (1.0f + __expf(-sg1))) * fmaxf(sf1, 0.0f);

#pragma unroll
                for (int st = 0; st < 4; st++) {
                    float t0 = __shfl_sync(0xFFFFFFFFu, v0, srcl[st]);
                    float t1 = __shfl_sync(0xFFFFFFFFu, v1, srcl[st]);
                    if (samep[st]) { v0 += t0; v1 += t1; }
                }
                if (head) {
                    int gcol = 32 * wn + 4 * nt + 2 * c0;
                    red_add_v2(dst + gcol, v0, v1);
                }
            }
        }

        if (!have_next) break;
        tile = next; ++it;
    }
}

// ---------------- launch ----------------
extern "C" void kernel_launch(void* const* d_in, const int* in_sizes, int n_in,
                              void* d_out, int out_size) {
    const float* sites  = (const float*)d_in[0];
    const float* bonds  = (const float*)d_in[1];
    const float* W_sig  = (const float*)d_in[2];
    const float* b_sig  = (const float*)d_in[3];
    const float* W_soft = (const float*)d_in[4];
    const float* b_soft = (const float*)d_in[5];
    const int*   idx1   = (const int*)d_in[6];
    const int*   idx2   = (const int*)d_in[7];
    float* out = (float*)d_out;

    cudaFuncSetAttribute(u_gemm_kernel, cudaFuncAttributeMaxDynamicSharedMemorySize, UG_SMEMF * 4);
    cudaFuncSetAttribute(edge_gate_kernel, cudaFuncAttributeMaxDynamicSharedMemorySize, EG_SMEMB);

    // 1) U = sites @ Wcat (fused: zero g_count + out=sites residual copy)
    u_gemm_kernel<<<dim3((N_NODES + 127) / 128, 4), 256, UG_SMEMF * 4>>>(
        sites, W_sig, b_sig, W_soft, b_soft, out);

    // 2-5) counting sort of edges by idx1
    hist_kernel<<<N_EDGES / 256, 256>>>(idx1);
    scan_a_kernel<<<NB50 / 256, 256>>>();
    scan_b_kernel<<<1, 256>>>();
    perm_kernel<<<N_EDGES / 256, 256>>>(idx1);

    // 6) edges (sorted): bonds[perm] @ Wb + two-phase epilogue (U-batch, gate+segreduce)
    edge_gate_kernel<<<GRID_EDGE, 256, EG_SMEMB>>>(
        bonds, W_sig, W_soft, idx1, idx2, out);
}